// round 8
// baseline (speedup 1.0000x reference)
#include <cuda_runtime.h>
#include <math.h>

#define N0 2048
#define N1 1024
#define K0 20               // 9 (A) + 9 (G) + 2 pad
#define K1 52               // 25 (A) + 25 (G) + 2 pad
#define K0_4 (K0 / 4)       // 5
#define K1_4 (K1 / 4)       // 13
// layer0: 64x128 tiles (micro 4x8), trapezoid by>=2bx : 272 tiles
// layer1: 64x64  tiles (micro 4x4), triangle  by>=bx  : 136 tiles
#define NBY0 (N0 / 64)      // 32
#define NBX0 (N0 / 128)     // 16
#define NTILE0 272
#define NTILE1 136
#define GRID_ALL (NTILE0 + NTILE1)   // 408
#define NPREP 12            // 12 prep blocks x 256 threads = 3072 matrices

// Scratch (allocation-free rule: __device__ globals, explicit zero-init)
// U row = [A(=inv) row-major, G=A^T A, pad]; V row = [-2*B^T, H=B B^T, pad]
// diff^2(i,j) = D + dot(U[i], V[j])
__device__ float    g_U0[N0 * K0];
__device__ float    g_V0[N0 * K0];
__device__ float    g_U1[N1 * K1];
__device__ float    g_V1[N1 * K1];
__device__ double   g_acc0 = 0.0;
__device__ double   g_acc1 = 0.0;
__device__ unsigned g_count = 0u;
__device__ volatile int g_flag[NPREP] = {};

typedef unsigned long long ull;

__device__ __forceinline__ void ffma2(ull& d, ull a, ull b) {
    asm("fma.rn.f32x2 %0, %1, %2, %0;" : "+l"(d) : "l"(a), "l"(b));
}
__device__ __forceinline__ float2 unpack2(ull v) {
    float2 f;
    asm("mov.b64 {%0, %1}, %2;" : "=f"(f.x), "=f"(f.y) : "l"(v));
    return f;
}

// branchless relu(1 - sqrt(d2)); zero whenever d2 >= 1
__device__ __forceinline__ float loss_term(float d2) {
    float s = fmaxf(d2, 1e-20f);
    return fmaxf(1.0f - s * __frsqrt_rn(s), 0.0f);
}

// ---------------------------------------------------------------------------
// Prep one layer-0 (3x3) matrix -> U/V rows
// ---------------------------------------------------------------------------
__device__ __forceinline__ void prep3(const float* __restrict__ in0, int i) {
    float a[9];
    float ss = 0.f;
#pragma unroll
    for (int k = 0; k < 9; k++) { a[k] = in0[i * 9 + k]; ss += a[k] * a[k]; }
    float inv_n = 1.0f / (sqrtf(ss) + 1e-8f);
#pragma unroll
    for (int k = 0; k < 9; k++) a[k] *= inv_n;

    float* V = &g_V0[i * K0];
#pragma unroll
    for (int r = 0; r < 3; r++)
#pragma unroll
        for (int k = 0; k < 3; k++) V[r * 3 + k] = -2.0f * a[k * 3 + r];
#pragma unroll
    for (int r = 0; r < 3; r++)
#pragma unroll
        for (int c = 0; c < 3; c++) {
            float s = 0.f;
#pragma unroll
            for (int k = 0; k < 3; k++) s += a[r * 3 + k] * a[c * 3 + k];
            V[9 + r * 3 + c] = s;
        }

    float c00 = a[4] * a[8] - a[5] * a[7];
    float c01 = a[5] * a[6] - a[3] * a[8];
    float c02 = a[3] * a[7] - a[4] * a[6];
    float det = a[0] * c00 + a[1] * c01 + a[2] * c02;
    float id  = 1.0f / det;

    float v[9];
    v[0] = c00 * id;
    v[1] = (a[2] * a[7] - a[1] * a[8]) * id;
    v[2] = (a[1] * a[5] - a[2] * a[4]) * id;
    v[3] = c01 * id;
    v[4] = (a[0] * a[8] - a[2] * a[6]) * id;
    v[5] = (a[2] * a[3] - a[0] * a[5]) * id;
    v[6] = c02 * id;
    v[7] = (a[1] * a[6] - a[0] * a[7]) * id;
    v[8] = (a[0] * a[4] - a[1] * a[3]) * id;

    float* U = &g_U0[i * K0];
#pragma unroll
    for (int k = 0; k < 9; k++) U[k] = v[k];
#pragma unroll
    for (int r = 0; r < 3; r++)
#pragma unroll
        for (int c = 0; c < 3; c++) {
            float s = 0.f;
#pragma unroll
            for (int k = 0; k < 3; k++) s += v[k * 3 + r] * v[k * 3 + c];
            U[9 + r * 3 + c] = s;
        }
#pragma unroll
    for (int k = 18; k < K0; k++) { U[k] = 0.f; V[k] = 0.f; }
}

// ---------------------------------------------------------------------------
// Prep one layer-1 (5x5) matrix (V-parts stored before GJ to limit pressure)
// ---------------------------------------------------------------------------
__device__ __forceinline__ void prep5(const float* __restrict__ in1, int i) {
    float m[5][10];
    float ss = 0.f;
#pragma unroll
    for (int r = 0; r < 5; r++)
#pragma unroll
        for (int c = 0; c < 5; c++) {
            float x = in1[i * 25 + r * 5 + c];
            m[r][c] = x; ss += x * x;
            m[r][c + 5] = (r == c) ? 1.0f : 0.0f;
        }
    float inv_n = 1.0f / (sqrtf(ss) + 1e-8f);
#pragma unroll
    for (int r = 0; r < 5; r++)
#pragma unroll
        for (int c = 0; c < 5; c++) m[r][c] *= inv_n;

    float* V = &g_V1[i * K1];
#pragma unroll
    for (int r = 0; r < 5; r++)
#pragma unroll
        for (int k = 0; k < 5; k++) V[r * 5 + k] = -2.0f * m[k][r];
#pragma unroll
    for (int r = 0; r < 5; r++)
#pragma unroll
        for (int c = 0; c < 5; c++) {
            float s = 0.f;
#pragma unroll
            for (int k = 0; k < 5; k++) s += m[r][k] * m[c][k];
            V[25 + r * 5 + c] = s;
        }

#pragma unroll
    for (int col = 0; col < 5; col++) {
#pragma unroll
        for (int r2 = 0; r2 < 5; r2++) {
            if (r2 > col) {
                bool sw = fabsf(m[r2][col]) > fabsf(m[col][col]);
#pragma unroll
                for (int c = 0; c < 10; c++) {
                    float x = m[col][c], y = m[r2][c];
                    m[col][c] = sw ? y : x;
                    m[r2][c]  = sw ? x : y;
                }
            }
        }
        float piv = 1.0f / m[col][col];
#pragma unroll
        for (int c = 0; c < 10; c++) m[col][c] *= piv;
#pragma unroll
        for (int r = 0; r < 5; r++) {
            if (r == col) continue;
            float f = m[r][col];
#pragma unroll
            for (int c = 0; c < 10; c++) m[r][c] = fmaf(-f, m[col][c], m[r][c]);
        }
    }

    float* U = &g_U1[i * K1];
#pragma unroll
    for (int r = 0; r < 5; r++)
#pragma unroll
        for (int c = 0; c < 5; c++) U[r * 5 + c] = m[r][c + 5];
#pragma unroll
    for (int r = 0; r < 5; r++)
#pragma unroll
        for (int c = 0; c < 5; c++) {
            float s = 0.f;
#pragma unroll
            for (int k = 0; k < 5; k++) s += m[k][r + 5] * m[k][c + 5];
            U[25 + r * 5 + c] = s;
        }
#pragma unroll
    for (int k = 50; k < K1; k++) { U[k] = 0.f; V[k] = 0.f; }
}

// ---------------------------------------------------------------------------
// Flag wait (tid 0 spins; then block barrier + fence = acquire)
// ---------------------------------------------------------------------------
__device__ __forceinline__ void wait_flags(int f0, int f1, int tid) {
    if (tid == 0) {
        while (g_flag[f0] == 0) __nanosleep(64);
        while (g_flag[f1] == 0) __nanosleep(64);
    }
    __syncthreads();
    __threadfence();
}

// ---------------------------------------------------------------------------
// Fill duplicated-U tile: Ud[k][...] holds [r0,r0,r1,r1,...] (128 floats/k).
// chunk(8 floats) = (row>>2) ^ k4 ; within chunk float2 at (row&3)*2.
// ---------------------------------------------------------------------------
template <int KV4>
__device__ __forceinline__ void fill_dupU(float* dst, const float4* src4,
                                          int row0, int tid) {
    for (int e = tid; e < 64 * KV4; e += 256) {
        int row = e / KV4, k4 = e - row * KV4;
        float4 u = src4[(row0 + row) * KV4 + k4];
        int base = (((row >> 2) ^ k4) << 3) + ((row & 3) << 1);
        float2* d0 = (float2*)&dst[(4 * k4 + 0) * 128 + base];
        float2* d1 = (float2*)&dst[(4 * k4 + 1) * 128 + base];
        float2* d2 = (float2*)&dst[(4 * k4 + 2) * 128 + base];
        float2* d3 = (float2*)&dst[(4 * k4 + 3) * 128 + base];
        *d0 = make_float2(u.x, u.x);
        *d1 = make_float2(u.y, u.y);
        *d2 = make_float2(u.z, u.z);
        *d3 = make_float2(u.w, u.w);
    }
}

// Swizzled V fill (as R6): dst[k][col], chunk(4 floats) = (row>>2) ^ (k4*CSH)
template <int KV4, int WIDTH, int CSH>
__device__ __forceinline__ void fill_V(float* dst, const float4* src4,
                                       int row0, int tid) {
    for (int e = tid; e < WIDTH * KV4; e += 256) {
        int row = e / KV4, k4 = e - row * KV4;
        float4 u = src4[(row0 + row) * KV4 + k4];
        int base = ((((row >> 2) ^ (k4 * CSH)) << 2) + (row & 3));
        dst[(4 * k4 + 0) * WIDTH + base] = u.x;
        dst[(4 * k4 + 1) * WIDTH + base] = u.y;
        dst[(4 * k4 + 2) * WIDTH + base] = u.z;
        dst[(4 * k4 + 3) * WIDTH + base] = u.w;
    }
}

// ---------------------------------------------------------------------------
// layer-0 tile: 64x128, micro 4x8, FFMA2
// ---------------------------------------------------------------------------
__device__ float body0(int t, float* smem, int tid) {
    int bx = 0;
    while (bx + 1 < NBX0 && (bx + 1) * (NBY0 + 1 - (bx + 1)) <= t) bx++;
    int by = 2 * bx + (t - bx * (NBY0 + 1 - bx));
    int i0 = by * 64, j0 = bx * 128;

    wait_flags(by >> 2, bx >> 1, tid);

    float* Ud = smem;                 // [K0][128] duplicated
    float* Vs = smem + K0 * 128;      // [K0][128]
    fill_dupU<K0_4>(Ud, (const float4*)g_U0, i0, tid);
    fill_V<K0_4, 128, 2>(Vs, (const float4*)g_V0, j0, tid);
    __syncthreads();

    int tx = tid & 15, ty = tid >> 4;
    ull acc[16];
#pragma unroll
    for (int q = 0; q < 16; q++) acc[q] = 0ull;

#pragma unroll
    for (int k = 0; k < K0; k++) {
        int kc = k >> 2;
        ulonglong2 aA = *(const ulonglong2*)&Ud[k * 128 + ((ty ^ kc) << 3)];     // r0r0,r1r1
        ulonglong2 aB = *(const ulonglong2*)&Ud[k * 128 + ((ty ^ kc) << 3) + 4]; // r2r2,r3r3
        int c0 = (2 * tx) ^ (2 * kc);
        ulonglong2 b0 = *(const ulonglong2*)&Vs[k * 128 + c0 * 4];        // cols 0..3
        ulonglong2 b1 = *(const ulonglong2*)&Vs[k * 128 + (c0 + 1) * 4];  // cols 4..7
        ffma2(acc[0],  aA.x, b0.x); ffma2(acc[1],  aA.x, b0.y);
        ffma2(acc[2],  aA.x, b1.x); ffma2(acc[3],  aA.x, b1.y);
        ffma2(acc[4],  aA.y, b0.x); ffma2(acc[5],  aA.y, b0.y);
        ffma2(acc[6],  aA.y, b1.x); ffma2(acc[7],  aA.y, b1.y);
        ffma2(acc[8],  aB.x, b0.x); ffma2(acc[9],  aB.x, b0.y);
        ffma2(acc[10], aB.x, b1.x); ffma2(acc[11], aB.x, b1.y);
        ffma2(acc[12], aB.y, b0.x); ffma2(acc[13], aB.y, b0.y);
        ffma2(acc[14], aB.y, b1.x); ffma2(acc[15], aB.y, b1.y);
    }

    float val = 0.f;
    if (by >= 2 * bx + 2) {
#pragma unroll
        for (int q = 0; q < 16; q++) {
            float2 f = unpack2(acc[q]);
            val += loss_term(3.0f + f.x);
            val += loss_term(3.0f + f.y);
        }
    } else {
        int ib = i0 + ty * 4, jb = j0 + tx * 8;
#pragma unroll
        for (int r = 0; r < 4; r++)
#pragma unroll
            for (int cp = 0; cp < 4; cp++) {
                float2 f = unpack2(acc[r * 4 + cp]);
                if (ib + r > jb + 2 * cp)     val += loss_term(3.0f + f.x);
                if (ib + r > jb + 2 * cp + 1) val += loss_term(3.0f + f.y);
            }
    }
    return val;
}

// ---------------------------------------------------------------------------
// layer-1 tile: 64x64, micro 4x4, FFMA2
// ---------------------------------------------------------------------------
__device__ float body1(int t, float* smem, int tid) {
    int by = 0;
    while ((by + 1) * (by + 2) / 2 <= t) by++;
    int bx = t - by * (by + 1) / 2;
    int i0 = by * 64, j0 = bx * 64;

    wait_flags(8 + (by >> 2), 8 + (bx >> 2), tid);

    float* Ud = smem;                 // [K1][128] duplicated
    float* Vs = smem + K1 * 128;      // [K1][64]
    fill_dupU<K1_4>(Ud, (const float4*)g_U1, i0, tid);
    fill_V<K1_4, 64, 1>(Vs, (const float4*)g_V1, j0, tid);
    __syncthreads();

    int tx = tid & 15, ty = tid >> 4;
    ull acc[8];
#pragma unroll
    for (int q = 0; q < 8; q++) acc[q] = 0ull;

#pragma unroll 4
    for (int k = 0; k < K1; k++) {
        int kc = k >> 2;
        ulonglong2 aA = *(const ulonglong2*)&Ud[k * 128 + ((ty ^ kc) << 3)];
        ulonglong2 aB = *(const ulonglong2*)&Ud[k * 128 + ((ty ^ kc) << 3) + 4];
        ulonglong2 b0 = *(const ulonglong2*)&Vs[k * 64 + ((tx ^ kc) << 2)];  // cols 0..3
        ffma2(acc[0], aA.x, b0.x); ffma2(acc[1], aA.x, b0.y);
        ffma2(acc[2], aA.y, b0.x); ffma2(acc[3], aA.y, b0.y);
        ffma2(acc[4], aB.x, b0.x); ffma2(acc[5], aB.x, b0.y);
        ffma2(acc[6], aB.y, b0.x); ffma2(acc[7], aB.y, b0.y);
    }

    float val = 0.f;
    if (by > bx) {
#pragma unroll
        for (int q = 0; q < 8; q++) {
            float2 f = unpack2(acc[q]);
            val += loss_term(5.0f + f.x);
            val += loss_term(5.0f + f.y);
        }
    } else {
        int ib = i0 + ty * 4, jb = j0 + tx * 4;
#pragma unroll
        for (int r = 0; r < 4; r++)
#pragma unroll
            for (int cp = 0; cp < 2; cp++) {
                float2 f = unpack2(acc[r * 2 + cp]);
                if (ib + r > jb + 2 * cp)     val += loss_term(5.0f + f.x);
                if (ib + r > jb + 2 * cp + 1) val += loss_term(5.0f + f.y);
            }
    }
    return val;
}

// ---------------------------------------------------------------------------
// Fused kernel: prep (blocks 0..11, 1 matrix/thread) + pair tiles + finalize
// ---------------------------------------------------------------------------
__global__ __launch_bounds__(256, 4) void fused_kernel(const float* __restrict__ in0,
                                                       const float* __restrict__ in1,
                                                       float* __restrict__ out) {
    __shared__ float smem[K1 * 128 + K1 * 64];   // 39.9 KB (layer1 worst case)
    int tid = threadIdx.x;
    int b = blockIdx.x;

    // ---- prep phase: 12 blocks x 256 threads = all 3072 matrices ----
    if (b < NPREP) {
        if (b < 8) prep3(in0, b * 256 + tid);
        else       prep5(in1, (b - 8) * 256 + tid);
        __syncthreads();
        if (tid == 0) {
            __threadfence();              // publish U/V before flag
            g_flag[b] = 1;
        }
    }

    // ---- pair phase: layer0 (light) tiles first so prep blocks get them ----
    bool layer0 = (b < NTILE0);
    float val = layer0 ? body0(b, smem, tid)
                       : body1(b - NTILE0, smem, tid);

#pragma unroll
    for (int o = 16; o > 0; o >>= 1)
        val += __shfl_down_sync(0xffffffffu, val, o);

    __syncthreads();   // smem main-loop reads done before reuse
    if ((tid & 31) == 0) smem[tid >> 5] = val;
    __syncthreads();

    if (tid == 0) {
        float s = 0.0f;
#pragma unroll
        for (int w = 0; w < 8; w++) s += smem[w];
        if (s != 0.0f)
            atomicAdd(layer0 ? &g_acc0 : &g_acc1, (double)s);
        __threadfence();
        unsigned done = atomicAdd(&g_count, 1u) + 1u;
        if (done == (unsigned)GRID_ALL) {
            double a0 = atomicAdd(&g_acc0, 0.0);
            double a1 = atomicAdd(&g_acc1, 0.0);
            double l0 = 2.0 * a0 / ((double)N0 * (double)(N0 - 1));
            double l1 = 2.0 * a1 / ((double)N1 * (double)(N1 - 1));
            out[0] = (float)(0.5 * (l0 + l1));
            // self-clean for the next graph replay (zero-invariant at entry)
            for (int q = 0; q < NPREP; q++) g_flag[q] = 0;
            g_acc0 = 0.0; g_acc1 = 0.0;
            __threadfence();
            g_count = 0u;
        }
    }
}

extern "C" void kernel_launch(void* const* d_in, const int* in_sizes, int n_in,
                              void* d_out, int out_size) {
    const float* k0 = (const float*)d_in[0];
    const float* k1 = (const float*)d_in[1];
    float* out = (float*)d_out;
    fused_kernel<<<GRID_ALL, 256>>>(k0, k1, out);
}

// round 9
// speedup vs baseline: 1.9792x; 1.9792x over previous
#include <cuda_runtime.h>
#include <math.h>

#define N0 2048
#define N1 1024
#define K0 20               // 9 (A) + 9 (G) + 2 pad
#define K1 52               // 25 (A) + 25 (G) + 2 pad
// layer0: 64x128 tiles (micro 4x8), trapezoid by>=2bx : 272 tiles
// layer1: 64x64  tiles (micro 4x4), triangle  by>=bx  : 136 tiles
#define NBY0 (N0 / 64)      // 32
#define NBX0 (N0 / 128)     // 16
#define NTILE0 272
#define NTILE1 136
#define GRID_ALL (NTILE0 + NTILE1)   // 408

// Only cross-block state: accumulators + completion counter (self-cleaned)
__device__ double   g_acc0 = 0.0;
__device__ double   g_acc1 = 0.0;
__device__ unsigned g_count = 0u;

// branchless relu(1 - sqrt(d2)); zero whenever d2 >= 1
__device__ __forceinline__ float loss_term(float d2) {
    float s = fmaxf(d2, 1e-20f);
    return fmaxf(1.0f - s * __frsqrt_rn(s), 0.0f);
}

// Swizzled K-major store:  dst[k][col] at  k*W + ((col>>2 ^ (k>>2)*CSH)<<2) + (col&3)
template <int WIDTH, int CSH>
__device__ __forceinline__ void sts_sw(float* dst, int col, int k, float v) {
    dst[k * WIDTH + ((((col >> 2) ^ ((k >> 2) * CSH)) << 2) + (col & 3))] = v;
}

// ---------------------------------------------------------------------------
// layer-0 prep (3x3): U-role (inverse + Gram) / V-role (no inversion needed)
// ---------------------------------------------------------------------------
template <int WIDTH, int CSH>
__device__ __forceinline__ void prep3_U(const float* __restrict__ in0, int i,
                                        float* dst, int col) {
    float a[9];
    float ss = 0.f;
#pragma unroll
    for (int k = 0; k < 9; k++) { a[k] = in0[i * 9 + k]; ss += a[k] * a[k]; }
    float inv_n = 1.0f / (sqrtf(ss) + 1e-8f);
#pragma unroll
    for (int k = 0; k < 9; k++) a[k] *= inv_n;

    float c00 = a[4] * a[8] - a[5] * a[7];
    float c01 = a[5] * a[6] - a[3] * a[8];
    float c02 = a[3] * a[7] - a[4] * a[6];
    float det = a[0] * c00 + a[1] * c01 + a[2] * c02;
    float id  = 1.0f / det;

    float v[9];
    v[0] = c00 * id;
    v[1] = (a[2] * a[7] - a[1] * a[8]) * id;
    v[2] = (a[1] * a[5] - a[2] * a[4]) * id;
    v[3] = c01 * id;
    v[4] = (a[0] * a[8] - a[2] * a[6]) * id;
    v[5] = (a[2] * a[3] - a[0] * a[5]) * id;
    v[6] = c02 * id;
    v[7] = (a[1] * a[6] - a[0] * a[7]) * id;
    v[8] = (a[0] * a[4] - a[1] * a[3]) * id;

#pragma unroll
    for (int k = 0; k < 9; k++) sts_sw<WIDTH, CSH>(dst, col, k, v[k]);
#pragma unroll
    for (int r = 0; r < 3; r++)
#pragma unroll
        for (int c = 0; c < 3; c++) {
            float s = 0.f;
#pragma unroll
            for (int k = 0; k < 3; k++) s += v[k * 3 + r] * v[k * 3 + c];
            sts_sw<WIDTH, CSH>(dst, col, 9 + r * 3 + c, s);
        }
#pragma unroll
    for (int k = 18; k < K0; k++) sts_sw<WIDTH, CSH>(dst, col, k, 0.f);
}

template <int WIDTH, int CSH>
__device__ __forceinline__ void prep3_V(const float* __restrict__ in0, int j,
                                        float* dst, int col) {
    float a[9];
    float ss = 0.f;
#pragma unroll
    for (int k = 0; k < 9; k++) { a[k] = in0[j * 9 + k]; ss += a[k] * a[k]; }
    float inv_n = 1.0f / (sqrtf(ss) + 1e-8f);
#pragma unroll
    for (int k = 0; k < 9; k++) a[k] *= inv_n;

#pragma unroll
    for (int r = 0; r < 3; r++)
#pragma unroll
        for (int k = 0; k < 3; k++)
            sts_sw<WIDTH, CSH>(dst, col, r * 3 + k, -2.0f * a[k * 3 + r]);
#pragma unroll
    for (int r = 0; r < 3; r++)
#pragma unroll
        for (int c = 0; c < 3; c++) {
            float s = 0.f;
#pragma unroll
            for (int k = 0; k < 3; k++) s += a[r * 3 + k] * a[c * 3 + k];
            sts_sw<WIDTH, CSH>(dst, col, 9 + r * 3 + c, s);
        }
#pragma unroll
    for (int k = 18; k < K0; k++) sts_sw<WIDTH, CSH>(dst, col, k, 0.f);
}

// ---------------------------------------------------------------------------
// layer-1 prep (5x5): U-role (pivoted GJ inverse + Gram) / V-role (no inverse)
// ---------------------------------------------------------------------------
template <int WIDTH, int CSH>
__device__ __forceinline__ void prep5_U(const float* __restrict__ in1, int i,
                                        float* dst, int col) {
    float m[5][10];
    float ss = 0.f;
#pragma unroll
    for (int r = 0; r < 5; r++)
#pragma unroll
        for (int c = 0; c < 5; c++) {
            float x = in1[i * 25 + r * 5 + c];
            m[r][c] = x; ss += x * x;
            m[r][c + 5] = (r == c) ? 1.0f : 0.0f;
        }
    float inv_n = 1.0f / (sqrtf(ss) + 1e-8f);
#pragma unroll
    for (int r = 0; r < 5; r++)
#pragma unroll
        for (int c = 0; c < 5; c++) m[r][c] *= inv_n;

#pragma unroll
    for (int col_ = 0; col_ < 5; col_++) {
#pragma unroll
        for (int r2 = 0; r2 < 5; r2++) {
            if (r2 > col_) {
                bool sw = fabsf(m[r2][col_]) > fabsf(m[col_][col_]);
#pragma unroll
                for (int c = 0; c < 10; c++) {
                    float x = m[col_][c], y = m[r2][c];
                    m[col_][c] = sw ? y : x;
                    m[r2][c]   = sw ? x : y;
                }
            }
        }
        float piv = 1.0f / m[col_][col_];
#pragma unroll
        for (int c = 0; c < 10; c++) m[col_][c] *= piv;
#pragma unroll
        for (int r = 0; r < 5; r++) {
            if (r == col_) continue;
            float f = m[r][col_];
#pragma unroll
            for (int c = 0; c < 10; c++) m[r][c] = fmaf(-f, m[col_][c], m[r][c]);
        }
    }

    // A = inv (columns 5..9 of m): write A then G = A^T A
#pragma unroll
    for (int r = 0; r < 5; r++)
#pragma unroll
        for (int c = 0; c < 5; c++)
            sts_sw<WIDTH, CSH>(dst, col, r * 5 + c, m[r][c + 5]);
#pragma unroll
    for (int r = 0; r < 5; r++)
#pragma unroll
        for (int c = 0; c < 5; c++) {
            float s = 0.f;
#pragma unroll
            for (int k = 0; k < 5; k++) s += m[k][r + 5] * m[k][c + 5];
            sts_sw<WIDTH, CSH>(dst, col, 25 + r * 5 + c, s);
        }
#pragma unroll
    for (int k = 50; k < K1; k++) sts_sw<WIDTH, CSH>(dst, col, k, 0.f);
}

template <int WIDTH, int CSH>
__device__ __forceinline__ void prep5_V(const float* __restrict__ in1, int j,
                                        float* dst, int col) {
    float b[25];
    float ss = 0.f;
#pragma unroll
    for (int k = 0; k < 25; k++) { b[k] = in1[j * 25 + k]; ss += b[k] * b[k]; }
    float inv_n = 1.0f / (sqrtf(ss) + 1e-8f);
#pragma unroll
    for (int k = 0; k < 25; k++) b[k] *= inv_n;

#pragma unroll
    for (int r = 0; r < 5; r++)
#pragma unroll
        for (int k = 0; k < 5; k++)
            sts_sw<WIDTH, CSH>(dst, col, r * 5 + k, -2.0f * b[k * 5 + r]);
#pragma unroll
    for (int r = 0; r < 5; r++)
#pragma unroll
        for (int c = 0; c < 5; c++) {
            float s = 0.f;
#pragma unroll
            for (int k = 0; k < 5; k++) s += b[r * 5 + k] * b[c * 5 + k];
            sts_sw<WIDTH, CSH>(dst, col, 25 + r * 5 + c, s);
        }
#pragma unroll
    for (int k = 50; k < K1; k++) sts_sw<WIDTH, CSH>(dst, col, k, 0.f);
}

// ---------------------------------------------------------------------------
// layer-0 tile: 64x128, micro 4x8, scalar FMA (proven best-issue form)
// ---------------------------------------------------------------------------
__device__ float body0(int t, float* smem, int tid,
                       const float* __restrict__ in0) {
    int bx = 0;
    while (bx + 1 < NBX0 && (bx + 1) * (NBY0 + 1 - (bx + 1)) <= t) bx++;
    int by = 2 * bx + (t - bx * (NBY0 + 1 - bx));
    int i0 = by * 64, j0 = bx * 128;

    float* Us = smem;                 // [K0][64]
    float* Vs = smem + K0 * 64;       // [K0][128]

    // in-block redundant prep (no inter-block sync)
    if (tid < 64)                     prep3_U<64, 1>(in0, i0 + tid, Us, tid);
    else if (tid < 192)               prep3_V<128, 2>(in0, j0 + tid - 64, Vs, tid - 64);
    __syncthreads();

    int tx = tid & 15, ty = tid >> 4;
    float acc[32];
#pragma unroll
    for (int q = 0; q < 32; q++) acc[q] = 0.f;

#pragma unroll
    for (int k = 0; k < K0; k++) {
        int kc = k >> 2;
        float4 a  = *(const float4*)&Us[k * 64 + ((ty ^ kc) << 2)];
        int c0 = (2 * tx) ^ (kc << 1);            // even; partner c0+1
        float4 bA = *(const float4*)&Vs[k * 128 + c0 * 4];
        float4 bB = *(const float4*)&Vs[k * 128 + (c0 + 1) * 4];
#pragma unroll
        for (int r = 0; r < 4; r++) {
            float av = (r == 0) ? a.x : (r == 1) ? a.y : (r == 2) ? a.z : a.w;
            acc[r * 8 + 0] = fmaf(av, bA.x, acc[r * 8 + 0]);
            acc[r * 8 + 1] = fmaf(av, bA.y, acc[r * 8 + 1]);
            acc[r * 8 + 2] = fmaf(av, bA.z, acc[r * 8 + 2]);
            acc[r * 8 + 3] = fmaf(av, bA.w, acc[r * 8 + 3]);
            acc[r * 8 + 4] = fmaf(av, bB.x, acc[r * 8 + 4]);
            acc[r * 8 + 5] = fmaf(av, bB.y, acc[r * 8 + 5]);
            acc[r * 8 + 6] = fmaf(av, bB.z, acc[r * 8 + 6]);
            acc[r * 8 + 7] = fmaf(av, bB.w, acc[r * 8 + 7]);
        }
    }

    float val = 0.f;
    if (by >= 2 * bx + 2) {
#pragma unroll
        for (int q = 0; q < 32; q++) val += loss_term(3.0f + acc[q]);
    } else {
        int ib = i0 + ty * 4, jb = j0 + tx * 8;
#pragma unroll
        for (int r = 0; r < 4; r++)
#pragma unroll
            for (int c = 0; c < 8; c++)
                if (ib + r > jb + c) val += loss_term(3.0f + acc[r * 8 + c]);
    }
    return val;
}

// ---------------------------------------------------------------------------
// layer-1 tile: 64x64, micro 4x4, scalar FMA
// ---------------------------------------------------------------------------
__device__ float body1(int t, float* smem, int tid,
                       const float* __restrict__ in1) {
    int by = 0;
    while ((by + 1) * (by + 2) / 2 <= t) by++;
    int bx = t - by * (by + 1) / 2;
    int i0 = by * 64, j0 = bx * 64;

    float* Us = smem;                 // [K1][64]
    float* Vs = smem + K1 * 64;       // [K1][64]

    if (tid < 64)                     prep5_U<64, 1>(in1, i0 + tid, Us, tid);
    else if (tid < 128)               prep5_V<64, 1>(in1, j0 + tid - 64, Vs, tid - 64);
    __syncthreads();

    int tx = tid & 15, ty = tid >> 4;
    float acc[16];
#pragma unroll
    for (int q = 0; q < 16; q++) acc[q] = 0.f;

#pragma unroll 4
    for (int k = 0; k < K1; k++) {
        int kc = k >> 2;
        float4 a = *(const float4*)&Us[k * 64 + ((ty ^ kc) << 2)];
        float4 b = *(const float4*)&Vs[k * 64 + ((tx ^ kc) << 2)];
        acc[0]  = fmaf(a.x, b.x, acc[0]);  acc[1]  = fmaf(a.x, b.y, acc[1]);
        acc[2]  = fmaf(a.x, b.z, acc[2]);  acc[3]  = fmaf(a.x, b.w, acc[3]);
        acc[4]  = fmaf(a.y, b.x, acc[4]);  acc[5]  = fmaf(a.y, b.y, acc[5]);
        acc[6]  = fmaf(a.y, b.z, acc[6]);  acc[7]  = fmaf(a.y, b.w, acc[7]);
        acc[8]  = fmaf(a.z, b.x, acc[8]);  acc[9]  = fmaf(a.z, b.y, acc[9]);
        acc[10] = fmaf(a.z, b.z, acc[10]); acc[11] = fmaf(a.z, b.w, acc[11]);
        acc[12] = fmaf(a.w, b.x, acc[12]); acc[13] = fmaf(a.w, b.y, acc[13]);
        acc[14] = fmaf(a.w, b.z, acc[14]); acc[15] = fmaf(a.w, b.w, acc[15]);
    }

    float val = 0.f;
    if (by > bx) {
#pragma unroll
        for (int q = 0; q < 16; q++) val += loss_term(5.0f + acc[q]);
    } else {
        int ib = i0 + ty * 4, jb = j0 + tx * 4;
#pragma unroll
        for (int r = 0; r < 4; r++)
#pragma unroll
            for (int c = 0; c < 4; c++)
                if (ib + r > jb + c) val += loss_term(5.0f + acc[r * 4 + c]);
    }
    return val;
}

// ---------------------------------------------------------------------------
// Fully self-contained blocks: redundant prep -> GEMM -> reduce -> finalize
// ---------------------------------------------------------------------------
__global__ __launch_bounds__(256, 4) void fused_kernel(const float* __restrict__ in0,
                                                       const float* __restrict__ in1,
                                                       float* __restrict__ out) {
    __shared__ float smem[2 * K1 * 64];   // 26.6 KB (layer1 worst case)
    int tid = threadIdx.x;
    int b = blockIdx.x;

    bool layer1 = (b < NTILE1);           // heavier tiles on low block ids
    float val = layer1 ? body1(b, smem, tid, in1)
                       : body0(b - NTILE1, smem, tid, in0);

#pragma unroll
    for (int o = 16; o > 0; o >>= 1)
        val += __shfl_down_sync(0xffffffffu, val, o);

    __syncthreads();   // smem main-loop reads done before reuse
    if ((tid & 31) == 0) smem[tid >> 5] = val;
    __syncthreads();

    if (tid == 0) {
        float s = 0.0f;
#pragma unroll
        for (int w = 0; w < 8; w++) s += smem[w];
        if (s != 0.0f)
            atomicAdd(layer1 ? &g_acc1 : &g_acc0, (double)s);
        __threadfence();
        unsigned done = atomicAdd(&g_count, 1u) + 1u;
        if (done == (unsigned)GRID_ALL) {
            double a0 = atomicAdd(&g_acc0, 0.0);
            double a1 = atomicAdd(&g_acc1, 0.0);
            double l0 = 2.0 * a0 / ((double)N0 * (double)(N0 - 1));
            double l1 = 2.0 * a1 / ((double)N1 * (double)(N1 - 1));
            out[0] = (float)(0.5 * (l0 + l1));
            // self-clean for the next graph replay (zero-invariant at entry)
            g_acc0 = 0.0; g_acc1 = 0.0;
            __threadfence();
            g_count = 0u;
        }
    }
}

extern "C" void kernel_launch(void* const* d_in, const int* in_sizes, int n_in,
                              void* d_out, int out_size) {
    const float* k0 = (const float*)d_in[0];
    const float* k1 = (const float*)d_in[1];
    float* out = (float*)d_out;
    fused_kernel<<<GRID_ALL, 256>>>(k0, k1, out);
}

// round 12
// speedup vs baseline: 2.1904x; 1.1067x over previous
#include <cuda_runtime.h>
#include <math.h>

#define N0 2048
#define N1 1024
#define K0 16               // 9 (A) + 3 (G diag) + 3 (2*G upper) + 1 pad
#define K1 40               // 25 (A) + 5 (G diag) + 10 (2*G upper)
// layer0: 64x128 tiles (micro 4x8), trapezoid by>=2bx : 272 tiles
// layer1: 64x64  tiles (micro 4x4), triangle  by>=bx  : 136 tiles
#define NBY0 (N0 / 64)      // 32
#define NBX0 (N0 / 128)     // 16
#define NTILE0 272
#define NTILE1 136
#define GRID_ALL (NTILE0 + NTILE1)   // 408

// Only cross-block state: accumulators + completion counter (self-cleaned)
__device__ double   g_acc0 = 0.0;
__device__ double   g_acc1 = 0.0;
__device__ unsigned g_count = 0u;

// relu(1 - sqrt(d2)) via rsqrt (only called on the rare d2 < 1 path)
__device__ __forceinline__ float loss_term(float d2) {
    float s = fmaxf(d2, 1e-20f);
    return fmaxf(1.0f - s * __frsqrt_rn(s), 0.0f);
}

// Swizzled K-major store:  dst[k][col] at  k*W + ((col>>2 ^ (k>>2)*CSH)<<2) + (col&3)
template <int WIDTH, int CSH>
__device__ __forceinline__ void sts_sw(float* dst, int col, int k, float v) {
    dst[k * WIDTH + ((((col >> 2) ^ ((k >> 2) * CSH)) << 2) + (col & 3))] = v;
}

// ---------------------------------------------------------------------------
// layer-0 prep (3x3).  U row: [A(9), G_diag(3), 2*G_upper(3), pad]
//                      V row: [-2*B^T(9), H_diag(3), H_upper(3), pad]
// dot(U,V) = -2 tr(AB) + tr(G H);  diff^2 = 3 + dot
// ---------------------------------------------------------------------------
template <int WIDTH, int CSH>
__device__ __forceinline__ void prep3_U(const float* __restrict__ in0, int i,
                                        float* dst, int col) {
    float a[9];
    float ss = 0.f;
#pragma unroll
    for (int k = 0; k < 9; k++) { a[k] = in0[i * 9 + k]; ss += a[k] * a[k]; }
    float inv_n = 1.0f / (sqrtf(ss) + 1e-8f);
#pragma unroll
    for (int k = 0; k < 9; k++) a[k] *= inv_n;

    float c00 = a[4] * a[8] - a[5] * a[7];
    float c01 = a[5] * a[6] - a[3] * a[8];
    float c02 = a[3] * a[7] - a[4] * a[6];
    float det = a[0] * c00 + a[1] * c01 + a[2] * c02;
    float id  = 1.0f / det;

    float v[9];
    v[0] = c00 * id;
    v[1] = (a[2] * a[7] - a[1] * a[8]) * id;
    v[2] = (a[1] * a[5] - a[2] * a[4]) * id;
    v[3] = c01 * id;
    v[4] = (a[0] * a[8] - a[2] * a[6]) * id;
    v[5] = (a[2] * a[3] - a[0] * a[5]) * id;
    v[6] = c02 * id;
    v[7] = (a[1] * a[6] - a[0] * a[7]) * id;
    v[8] = (a[0] * a[4] - a[1] * a[3]) * id;

#pragma unroll
    for (int k = 0; k < 9; k++) sts_sw<WIDTH, CSH>(dst, col, k, v[k]);
    // G = A^T A, symmetric: diag then doubled upper (01, 02, 12)
#pragma unroll
    for (int d = 0; d < 3; d++) {
        float s = 0.f;
#pragma unroll
        for (int k = 0; k < 3; k++) s += v[k * 3 + d] * v[k * 3 + d];
        sts_sw<WIDTH, CSH>(dst, col, 9 + d, s);
    }
    {
        int idx = 0;
#pragma unroll
        for (int r = 0; r < 3; r++)
#pragma unroll
            for (int c = r + 1; c < 3; c++) {
                float s = 0.f;
#pragma unroll
                for (int k = 0; k < 3; k++) s += v[k * 3 + r] * v[k * 3 + c];
                sts_sw<WIDTH, CSH>(dst, col, 12 + idx, 2.0f * s);
                idx++;
            }
    }
    sts_sw<WIDTH, CSH>(dst, col, 15, 0.f);
}

template <int WIDTH, int CSH>
__device__ __forceinline__ void prep3_V(const float* __restrict__ in0, int j,
                                        float* dst, int col) {
    float a[9];
    float ss = 0.f;
#pragma unroll
    for (int k = 0; k < 9; k++) { a[k] = in0[j * 9 + k]; ss += a[k] * a[k]; }
    float inv_n = 1.0f / (sqrtf(ss) + 1e-8f);
#pragma unroll
    for (int k = 0; k < 9; k++) a[k] *= inv_n;

#pragma unroll
    for (int r = 0; r < 3; r++)
#pragma unroll
        for (int k = 0; k < 3; k++)
            sts_sw<WIDTH, CSH>(dst, col, r * 3 + k, -2.0f * a[k * 3 + r]);
    // H = B B^T, symmetric: diag then upper (01, 02, 12)
#pragma unroll
    for (int d = 0; d < 3; d++) {
        float s = 0.f;
#pragma unroll
        for (int k = 0; k < 3; k++) s += a[d * 3 + k] * a[d * 3 + k];
        sts_sw<WIDTH, CSH>(dst, col, 9 + d, s);
    }
    {
        int idx = 0;
#pragma unroll
        for (int r = 0; r < 3; r++)
#pragma unroll
            for (int c = r + 1; c < 3; c++) {
                float s = 0.f;
#pragma unroll
                for (int k = 0; k < 3; k++) s += a[r * 3 + k] * a[c * 3 + k];
                sts_sw<WIDTH, CSH>(dst, col, 12 + idx, s);
                idx++;
            }
    }
    sts_sw<WIDTH, CSH>(dst, col, 15, 0.f);
}

// ---------------------------------------------------------------------------
// layer-1 prep (5x5).  U row: [A(25), G_diag(5), 2*G_upper(10)]  (K1 = 40)
//                      V row: [-2*B^T(25), H_diag(5), H_upper(10)]
// ---------------------------------------------------------------------------
template <int WIDTH, int CSH>
__device__ __forceinline__ void prep5_U(const float* __restrict__ in1, int i,
                                        float* dst, int col) {
    float m[5][10];
    float ss = 0.f;
#pragma unroll
    for (int r = 0; r < 5; r++)
#pragma unroll
        for (int c = 0; c < 5; c++) {
            float x = in1[i * 25 + r * 5 + c];
            m[r][c] = x; ss += x * x;
            m[r][c + 5] = (r == c) ? 1.0f : 0.0f;
        }
    float inv_n = 1.0f / (sqrtf(ss) + 1e-8f);
#pragma unroll
    for (int r = 0; r < 5; r++)
#pragma unroll
        for (int c = 0; c < 5; c++) m[r][c] *= inv_n;

#pragma unroll
    for (int col_ = 0; col_ < 5; col_++) {
#pragma unroll
        for (int r2 = 0; r2 < 5; r2++) {
            if (r2 > col_) {
                bool sw = fabsf(m[r2][col_]) > fabsf(m[col_][col_]);
#pragma unroll
                for (int c = 0; c < 10; c++) {
                    float x = m[col_][c], y = m[r2][c];
                    m[col_][c] = sw ? y : x;
                    m[r2][c]   = sw ? x : y;
                }
            }
        }
        float piv = 1.0f / m[col_][col_];
#pragma unroll
        for (int c = 0; c < 10; c++) m[col_][c] *= piv;
#pragma unroll
        for (int r = 0; r < 5; r++) {
            if (r == col_) continue;
            float f = m[r][col_];
#pragma unroll
            for (int c = 0; c < 10; c++) m[r][c] = fmaf(-f, m[col_][c], m[r][c]);
        }
    }

    // A = inv (columns 5..9 of m)
#pragma unroll
    for (int r = 0; r < 5; r++)
#pragma unroll
        for (int c = 0; c < 5; c++)
            sts_sw<WIDTH, CSH>(dst, col, r * 5 + c, m[r][c + 5]);
    // G = A^T A: diag, then doubled upper (lexicographic r<c)
#pragma unroll
    for (int d = 0; d < 5; d++) {
        float s = 0.f;
#pragma unroll
        for (int k = 0; k < 5; k++) s += m[k][d + 5] * m[k][d + 5];
        sts_sw<WIDTH, CSH>(dst, col, 25 + d, s);
    }
    {
        int idx = 0;
#pragma unroll
        for (int r = 0; r < 5; r++)
#pragma unroll
            for (int c = r + 1; c < 5; c++) {
                float s = 0.f;
#pragma unroll
                for (int k = 0; k < 5; k++) s += m[k][r + 5] * m[k][c + 5];
                sts_sw<WIDTH, CSH>(dst, col, 30 + idx, 2.0f * s);
                idx++;
            }
    }
}

template <int WIDTH, int CSH>
__device__ __forceinline__ void prep5_V(const float* __restrict__ in1, int j,
                                        float* dst, int col) {
    float b[25];
    float ss = 0.f;
#pragma unroll
    for (int k = 0; k < 25; k++) { b[k] = in1[j * 25 + k]; ss += b[k] * b[k]; }
    float inv_n = 1.0f / (sqrtf(ss) + 1e-8f);
#pragma unroll
    for (int k = 0; k < 25; k++) b[k] *= inv_n;

#pragma unroll
    for (int r = 0; r < 5; r++)
#pragma unroll
        for (int k = 0; k < 5; k++)
            sts_sw<WIDTH, CSH>(dst, col, r * 5 + k, -2.0f * b[k * 5 + r]);
    // H = B B^T: diag, then upper
#pragma unroll
    for (int d = 0; d < 5; d++) {
        float s = 0.f;
#pragma unroll
        for (int k = 0; k < 5; k++) s += b[d * 5 + k] * b[d * 5 + k];
        sts_sw<WIDTH, CSH>(dst, col, 25 + d, s);
    }
    {
        int idx = 0;
#pragma unroll
        for (int r = 0; r < 5; r++)
#pragma unroll
            for (int c = r + 1; c < 5; c++) {
                float s = 0.f;
#pragma unroll
                for (int k = 0; k < 5; k++) s += b[r * 5 + k] * b[c * 5 + k];
                sts_sw<WIDTH, CSH>(dst, col, 30 + idx, s);
                idx++;
            }
    }
}

// ---------------------------------------------------------------------------
// layer-0 tile: 64x128, micro 4x8, scalar FMA + min-scan early-out epilogue
// ---------------------------------------------------------------------------
__device__ float body0(int t, float* smem, int tid,
                       const float* __restrict__ in0) {
    int bx = 0;
    while (bx + 1 < NBX0 && (bx + 1) * (NBY0 + 1 - (bx + 1)) <= t) bx++;
    int by = 2 * bx + (t - bx * (NBY0 + 1 - bx));
    int i0 = by * 64, j0 = bx * 128;

    float* Us = smem;                 // [K0][64]
    float* Vs = smem + K0 * 64;       // [K0][128]

    // in-block redundant prep (no inter-block sync)
    if (tid < 64)                     prep3_U<64, 1>(in0, i0 + tid, Us, tid);
    else if (tid < 192)               prep3_V<128, 2>(in0, j0 + tid - 64, Vs, tid - 64);
    __syncthreads();

    int tx = tid & 15, ty = tid >> 4;
    float acc[32];
#pragma unroll
    for (int q = 0; q < 32; q++) acc[q] = 0.f;

#pragma unroll
    for (int k = 0; k < K0; k++) {
        int kc = k >> 2;
        float4 a  = *(const float4*)&Us[k * 64 + ((ty ^ kc) << 2)];
        int c0 = (2 * tx) ^ (kc << 1);            // even; partner c0+1
        float4 bA = *(const float4*)&Vs[k * 128 + c0 * 4];
        float4 bB = *(const float4*)&Vs[k * 128 + (c0 + 1) * 4];
#pragma unroll
        for (int r = 0; r < 4; r++) {
            float av = (r == 0) ? a.x : (r == 1) ? a.y : (r == 2) ? a.z : a.w;
            acc[r * 8 + 0] = fmaf(av, bA.x, acc[r * 8 + 0]);
            acc[r * 8 + 1] = fmaf(av, bA.y, acc[r * 8 + 1]);
            acc[r * 8 + 2] = fmaf(av, bA.z, acc[r * 8 + 2]);
            acc[r * 8 + 3] = fmaf(av, bA.w, acc[r * 8 + 3]);
            acc[r * 8 + 4] = fmaf(av, bB.x, acc[r * 8 + 4]);
            acc[r * 8 + 5] = fmaf(av, bB.y, acc[r * 8 + 5]);
            acc[r * 8 + 6] = fmaf(av, bB.z, acc[r * 8 + 6]);
            acc[r * 8 + 7] = fmaf(av, bB.w, acc[r * 8 + 7]);
        }
    }

    // min-scan: any d2 = 3 + acc < 1  <=>  min(acc) < -2
    float mn = acc[0];
#pragma unroll
    for (int q = 1; q < 32; q++) mn = fminf(mn, acc[q]);

    float val = 0.f;
    if (mn < -2.0f) {                     // rare: some pair contributes
        if (by >= 2 * bx + 2) {
#pragma unroll
            for (int q = 0; q < 32; q++) val += loss_term(3.0f + acc[q]);
        } else {
            int ib = i0 + ty * 4, jb = j0 + tx * 8;
#pragma unroll
            for (int r = 0; r < 4; r++)
#pragma unroll
                for (int c = 0; c < 8; c++)
                    if (ib + r > jb + c) val += loss_term(3.0f + acc[r * 8 + c]);
        }
    }
    return val;
}

// ---------------------------------------------------------------------------
// layer-1 tile: 64x64, micro 4x4, scalar FMA + min-scan early-out epilogue
// ---------------------------------------------------------------------------
__device__ float body1(int t, float* smem, int tid,
                       const float* __restrict__ in1) {
    int by = 0;
    while ((by + 1) * (by + 2) / 2 <= t) by++;
    int bx = t - by * (by + 1) / 2;
    int i0 = by * 64, j0 = bx * 64;

    float* Us = smem;                 // [K1][64]
    float* Vs = smem + K1 * 64;       // [K1][64]

    if (tid < 64)                     prep5_U<64, 1>(in1, i0 + tid, Us, tid);
    else if (tid < 128)               prep5_V<64, 1>(in1, j0 + tid - 64, Vs, tid - 64);
    __syncthreads();

    int tx = tid & 15, ty = tid >> 4;
    float acc[16];
#pragma unroll
    for (int q = 0; q < 16; q++) acc[q] = 0.f;

#pragma unroll 4
    for (int k = 0; k < K1; k++) {
        int kc = k >> 2;
        float4 a = *(const float4*)&Us[k * 64 + ((ty ^ kc) << 2)];
        float4 b = *(const float4*)&Vs[k * 64 + ((tx ^ kc) << 2)];
        acc[0]  = fmaf(a.x, b.x, acc[0]);  acc[1]  = fmaf(a.x, b.y, acc[1]);
        acc[2]  = fmaf(a.x, b.z, acc[2]);  acc[3]  = fmaf(a.x, b.w, acc[3]);
        acc[4]  = fmaf(a.y, b.x, acc[4]);  acc[5]  = fmaf(a.y, b.y, acc[5]);
        acc[6]  = fmaf(a.y, b.z, acc[6]);  acc[7]  = fmaf(a.y, b.w, acc[7]);
        acc[8]  = fmaf(a.z, b.x, acc[8]);  acc[9]  = fmaf(a.z, b.y, acc[9]);
        acc[10] = fmaf(a.z, b.z, acc[10]); acc[11] = fmaf(a.z, b.w, acc[11]);
        acc[12] = fmaf(a.w, b.x, acc[12]); acc[13] = fmaf(a.w, b.y, acc[13]);
        acc[14] = fmaf(a.w, b.z, acc[14]); acc[15] = fmaf(a.w, b.w, acc[15]);
    }

    // min-scan: any d2 = 5 + acc < 1  <=>  min(acc) < -4
    float mn = acc[0];
#pragma unroll
    for (int q = 1; q < 16; q++) mn = fminf(mn, acc[q]);

    float val = 0.f;
    if (mn < -4.0f) {
        if (by > bx) {
#pragma unroll
            for (int q = 0; q < 16; q++) val += loss_term(5.0f + acc[q]);
        } else {
            int ib = i0 + ty * 4, jb = j0 + tx * 4;
#pragma unroll
            for (int r = 0; r < 4; r++)
#pragma unroll
                for (int c = 0; c < 4; c++)
                    if (ib + r > jb + c) val += loss_term(5.0f + acc[r * 4 + c]);
        }
    }
    return val;
}

// ---------------------------------------------------------------------------
// Fully self-contained blocks: redundant prep -> GEMM -> reduce -> finalize
// ---------------------------------------------------------------------------
__global__ __launch_bounds__(256, 4) void fused_kernel(const float* __restrict__ in0,
                                                       const float* __restrict__ in1,
                                                       float* __restrict__ out) {
    __shared__ float smem[2 * K1 * 64];   // 20 KB (layer1 worst case)
    int tid = threadIdx.x;
    int b = blockIdx.x;

    bool layer1 = (b < NTILE1);           // heavier tiles on low block ids
    float val = layer1 ? body1(b, smem, tid, in1)
                       : body0(b - NTILE1, smem, tid, in0);

#pragma unroll
    for (int o = 16; o > 0; o >>= 1)
        val += __shfl_down_sync(0xffffffffu, val, o);

    __syncthreads();   // smem main-loop reads done before reuse
    if ((tid & 31) == 0) smem[tid >> 5] = val;
    __syncthreads();

    if (tid == 0) {
        float s = 0.0f;
#pragma unroll
        for (int w = 0; w < 8; w++) s += smem[w];
        if (s != 0.0f)
            atomicAdd(layer1 ? &g_acc1 : &g_acc0, (double)s);
        __threadfence();
        unsigned done = atomicAdd(&g_count, 1u) + 1u;
        if (done == (unsigned)GRID_ALL) {
            double a0 = atomicAdd(&g_acc0, 0.0);
            double a1 = atomicAdd(&g_acc1, 0.0);
            double l0 = 2.0 * a0 / ((double)N0 * (double)(N0 - 1));
            double l1 = 2.0 * a1 / ((double)N1 * (double)(N1 - 1));
            out[0] = (float)(0.5 * (l0 + l1));
            // self-clean for the next graph replay (zero-invariant at entry)
            g_acc0 = 0.0; g_acc1 = 0.0;
            __threadfence();
            g_count = 0u;
        }
    }
}

extern "C" void kernel_launch(void* const* d_in, const int* in_sizes, int n_in,
                              void* d_out, int out_size) {
    const float* k0 = (const float*)d_in[0];
    const float* k1 = (const float*)d_in[1];
    float* out = (float*)d_out;
    fused_kernel<<<GRID_ALL, 256>>>(k0, k1, out);
}